// round 11
// baseline (speedup 1.0000x reference)
#include <cuda_runtime.h>

#define NROWS 8192
#define NDIM  512
#define ND4   128      // NDIM/4
#define NTOP  100
#define NBLK  128
#define NTHR  1024
#define NBIN  4096     // 12-bit histogram
#define CAP   1536     // candidate capacity (expected ~130)

#define SMEM_X_BYTES   (64 * ND4 * 16)          // 128 KB: block's 64 rows
#define SMEM_ACC_BYTES (32 * ND4 * 16)          // 64 KB: 32 warp partials
#define SMEM_TOTAL     (SMEM_X_BYTES + SMEM_ACC_BYTES)

__device__ float4 g_s4[ND4];                    // atomic-accumulated column sum
__device__ int   g_hist[NBIN];                  // atomic-accumulated key histogram
__device__ unsigned int g_key[NROWS];
__device__ unsigned int g_sync[3];  // [0] s ctr, [1] key+hist ctr, [2] done ctr

__device__ __forceinline__ unsigned int vload(unsigned int* p) {
    return *(volatile unsigned int*)p;
}

__global__ void __launch_bounds__(NTHR, 1) kFused(const float4* __restrict__ x4,
                                                  float* __restrict__ out,
                                                  float4* __restrict__ out4,
                                                  int out_size) {
    extern __shared__ char smem_raw[];
    float4* xs   = (float4*)smem_raw;                       // [64][ND4]
    float4* sacc = (float4*)(smem_raw + SMEM_X_BYTES);      // [32][ND4]

    __shared__ int swarp[32];
    __shared__ int sh_B, sh_ncand;
    __shared__ int s_row;

    const int t    = threadIdx.x;
    const int wid  = t >> 5;          // 0..31
    const int lane = t & 31;
    const int lrow0 = wid * 2;

    // ===== P1: stream 2 rows/warp to smem, per-row 1/||x||, colsum partial ===
    float rinv0, rinv1;
    {
        const float4* r0 = x4 + (size_t)(blockIdx.x * 64 + lrow0) * ND4;
        const float4* r1 = r0 + ND4;
        float4 v0[4], v1[4];
        #pragma unroll
        for (int k = 0; k < 4; ++k) v0[k] = r0[lane + 32 * k];
        #pragma unroll
        for (int k = 0; k < 4; ++k) v1[k] = r1[lane + 32 * k];
        #pragma unroll
        for (int k = 0; k < 4; ++k) xs[lrow0 * ND4 + lane + 32 * k] = v0[k];
        #pragma unroll
        for (int k = 0; k < 4; ++k) xs[(lrow0 + 1) * ND4 + lane + 32 * k] = v1[k];

        float sq0 = 0.f, sq1 = 0.f;
        #pragma unroll
        for (int k = 0; k < 4; ++k) {
            sq0 += v0[k].x*v0[k].x + v0[k].y*v0[k].y + v0[k].z*v0[k].z + v0[k].w*v0[k].w;
            sq1 += v1[k].x*v1[k].x + v1[k].y*v1[k].y + v1[k].z*v1[k].z + v1[k].w*v1[k].w;
        }
        #pragma unroll
        for (int o = 16; o; o >>= 1) {
            sq0 += __shfl_xor_sync(0xffffffffu, sq0, o);
            sq1 += __shfl_xor_sync(0xffffffffu, sq1, o);
        }
        rinv0 = rsqrtf(sq0); rinv0 = rinv0 * (1.5f - 0.5f * sq0 * rinv0 * rinv0);
        rinv1 = rsqrtf(sq1); rinv1 = rinv1 * (1.5f - 0.5f * sq1 * rinv1 * rinv1);

        // warp partial -> its own smem buffer (no cross-warp staging)
        #pragma unroll
        for (int k = 0; k < 4; ++k) {
            float4 a;
            a.x = fmaf(v0[k].x, rinv0, v1[k].x * rinv1);
            a.y = fmaf(v0[k].y, rinv0, v1[k].y * rinv1);
            a.z = fmaf(v0[k].z, rinv0, v1[k].z * rinv1);
            a.w = fmaf(v0[k].w, rinv0, v1[k].w * rinv1);
            sacc[wid * ND4 + lane + 32 * k] = a;
        }
        __syncthreads();

        // 1024 threads: group g sums 4 buffers for dim d, REDs to g_s4
        int d = t & (ND4 - 1);
        int g = t >> 7;                  // 0..7
        float4 s = sacc[(g * 4) * ND4 + d];
        #pragma unroll
        for (int w = 1; w < 4; ++w) {
            float4 u = sacc[(g * 4 + w) * ND4 + d];
            s.x += u.x; s.y += u.y; s.z += u.z; s.w += u.w;
        }
        float* gs = (float*)&g_s4[d];
        atomicAdd(gs + 0, s.x);
        atomicAdd(gs + 1, s.y);
        atomicAdd(gs + 2, s.z);
        atomicAdd(gs + 3, s.w);
    }

    // ===== SYNC 1: counter == NBLK  =>  all REDs to g_s complete ==============
    __syncthreads();
    if (t == 0) {
        __threadfence();
        atomicAdd(&g_sync[0], 1u);
        while (vload(&g_sync[0]) < NBLK) __nanosleep(32);
        __threadfence();
    }
    __syncthreads();

    // ===== P3: s direct from L2; dots from smem x; keys + global hist ========
    {
        float4 sv[4];
        #pragma unroll
        for (int k = 0; k < 4; ++k) sv[k] = g_s4[lane + 32 * k];

        float dot0 = 0.f, dot1 = 0.f;
        #pragma unroll
        for (int k = 0; k < 4; ++k) {
            float4 a = xs[lrow0 * ND4 + lane + 32 * k];
            float4 b = xs[(lrow0 + 1) * ND4 + lane + 32 * k];
            dot0 = fmaf(a.x, sv[k].x, dot0); dot0 = fmaf(a.y, sv[k].y, dot0);
            dot0 = fmaf(a.z, sv[k].z, dot0); dot0 = fmaf(a.w, sv[k].w, dot0);
            dot1 = fmaf(b.x, sv[k].x, dot1); dot1 = fmaf(b.y, sv[k].y, dot1);
            dot1 = fmaf(b.z, sv[k].z, dot1); dot1 = fmaf(b.w, sv[k].w, dot1);
        }
        #pragma unroll
        for (int o = 16; o; o >>= 1) {
            dot0 += __shfl_down_sync(0xffffffffu, dot0, o);
            dot1 += __shfl_down_sync(0xffffffffu, dot1, o);
        }
        if (lane == 0) {
            unsigned int u0 = __float_as_uint(dot0 * rinv0);
            unsigned int u1 = __float_as_uint(dot1 * rinv1);
            u0 = (u0 & 0x80000000u) ? ~u0 : (u0 | 0x80000000u);
            u1 = (u1 & 0x80000000u) ? ~u1 : (u1 | 0x80000000u);
            int row = blockIdx.x * 64 + lrow0;
            *(uint2*)&g_key[row] = make_uint2(u0, u1);
            atomicAdd(&g_hist[u0 >> 20], 1);
            atomicAdd(&g_hist[u1 >> 20], 1);
        }
    }

    // ===== SYNC 2: keys + hist visible. Blocks >= NTOP just arrive. ===========
    __syncthreads();
    if (t == 0) { __threadfence(); atomicAdd(&g_sync[1], 1u); }

    if (blockIdx.x < NTOP) {
        if (t == 0) {
            while (vload(&g_sync[1]) < NBLK) __nanosleep(32);
            __threadfence();
        }
        __syncthreads();

        // ===== P4: hist scan -> boundary bin B; collect; exact stable rank ====
        unsigned int* ckey = (unsigned int*)sacc;          // [CAP]
        int*          cidx = (int*)sacc + CAP;             // [CAP]

        uint4 ka = ((const uint4*)g_key)[t];               // keys 4t..4t+3
        uint4 kb = ((const uint4*)g_key)[t + 1024];        // keys 4096+4t..
        uint4 hv = ((const uint4*)g_hist)[t];              // bins 4t..4t+3
        if (t == 0) sh_ncand = 0;

        int lsum = hv.x + hv.y + hv.z + hv.w;
        int v = lsum;
        #pragma unroll
        for (int o = 1; o < 32; o <<= 1) {
            int u = __shfl_up_sync(0xffffffffu, v, o);
            if (lane >= o) v += u;
        }
        if (lane == 31) swarp[wid] = v;
        __syncthreads();
        if (t < 32) {
            int w = swarp[t];
            int vv = w;
            #pragma unroll
            for (int o = 1; o < 32; o <<= 1) {
                int u = __shfl_up_sync(0xffffffffu, vv, o);
                if (lane >= o) vv += u;
            }
            swarp[t] = vv - w;                  // exclusive warp offset
        }
        __syncthreads();
        {
            int c = swarp[wid] + (v - lsum);    // exclusive prefix for bin 4t
            int hh[4] = {(int)hv.x, (int)hv.y, (int)hv.z, (int)hv.w};
            #pragma unroll
            for (int i = 0; i < 4; ++i) {
                int c2 = c + hh[i];
                if (c < NTOP && c2 >= NTOP) sh_B = 4 * t + i;
                c = c2;
            }
        }
        __syncthreads();
        unsigned int B = (unsigned int)sh_B;

        unsigned int keys[8] = {ka.x, ka.y, ka.z, ka.w, kb.x, kb.y, kb.z, kb.w};
        #pragma unroll
        for (int j = 0; j < 8; ++j) {
            if ((keys[j] >> 20) <= B) {
                int p = atomicAdd(&sh_ncand, 1);
                if (p < CAP) {
                    ckey[p] = keys[j];
                    cidx[p] = (j < 4) ? (4 * t + j) : (4096 + 4 * t + (j - 4));
                }
            }
        }
        __syncthreads();
        int nc = sh_ncand < CAP ? sh_ncand : CAP;

        if (t < nc) {
            unsigned int mk = ckey[t];
            int mi = cidx[t];
            int rank = 0;
            for (int j = 0; j < nc; ++j)
                rank += (ckey[j] < mk || (ckey[j] == mk && cidx[j] < mi)) ? 1 : 0;
            if (rank == blockIdx.x) s_row = mi;
        }
        __syncthreads();

        // ===== P5: write this block's row + index ==============================
        int row = s_row;
        if (t < ND4) {
            int e = blockIdx.x * ND4 + t;
            if (4 * e + 4 <= out_size)
                out4[e] = x4[(size_t)row * ND4 + t];
        }
        if (t == 0 && NTOP * NDIM + blockIdx.x < out_size)
            out[NTOP * NDIM + blockIdx.x] = (float)row;
    }

    // ===== epilogue: last finisher resets g_s, g_hist, sync for replay ========
    __shared__ int s_reset;
    if (t == 0) {
        __threadfence();
        s_reset = (atomicAdd(&g_sync[2], 1u) == NBLK - 1) ? 1 : 0;
    }
    __syncthreads();
    if (s_reset) {
        if (t < ND4) g_s4[t] = make_float4(0.f, 0.f, 0.f, 0.f);
        #pragma unroll
        for (int j = 0; j < NBIN / NTHR; ++j) g_hist[t + NTHR * j] = 0;
        __syncthreads();
        if (t == 0) {
            *(volatile unsigned int*)&g_sync[0] = 0;
            *(volatile unsigned int*)&g_sync[1] = 0;
            __threadfence();
            *(volatile unsigned int*)&g_sync[2] = 0;
        }
    }
}

extern "C" void kernel_launch(void* const* d_in, const int* in_sizes, int n_in,
                              void* d_out, int out_size) {
    const float4* x4 = (const float4*)d_in[0];
    cudaFuncSetAttribute(kFused, cudaFuncAttributeMaxDynamicSharedMemorySize,
                         SMEM_TOTAL);
    kFused<<<NBLK, NTHR, SMEM_TOTAL>>>(x4, (float*)d_out, (float4*)d_out, out_size);
}

// round 12
// speedup vs baseline: 2.4725x; 2.4725x over previous
#include <cuda_runtime.h>

#define NROWS 8192
#define NDIM  512
#define ND4   128      // NDIM/4
#define NTOP  100
#define NBLK  128
#define NTHR  1024
#define NBIN  4096     // 12-bit histogram
#define CAP   1536     // candidate capacity (expected ~130)

#define SMEM_X_BYTES   (64 * ND4 * 16)          // 128 KB: block's 64 rows
#define SMEM_ACC_BYTES (16 * ND4 * 16)          // 32 KB scratch
#define SMEM_TOTAL     (SMEM_X_BYTES + SMEM_ACC_BYTES)

__device__ float4 g_s4[ND4];                    // atomic-accumulated column sum
__device__ int   g_hist[NBIN];                  // atomic-accumulated key histogram
__device__ unsigned int g_key[NROWS];
__device__ unsigned int g_sync[3];  // [0] s ctr, [1] key+hist ctr, [2] done ctr

__device__ __forceinline__ unsigned int vload(unsigned int* p) {
    return *(volatile unsigned int*)p;
}

__global__ void __launch_bounds__(NTHR, 1) kFused(const float4* __restrict__ x4,
                                                  float* __restrict__ out,
                                                  float4* __restrict__ out4,
                                                  int out_size) {
    extern __shared__ char smem_raw[];
    float4* xs    = (float4*)smem_raw;                       // [64][ND4]
    float4* sacc  = (float4*)(smem_raw + SMEM_X_BYTES);      // [16][ND4]
    float*  saccf = (float*)sacc;

    __shared__ int swarp[32];
    __shared__ int sh_B, sh_ncand;
    __shared__ int s_row;

    const int t    = threadIdx.x;
    const int wid  = t >> 5;          // 0..31
    const int lane = t & 31;
    const int lrow0 = wid * 2;

    // ===== P1: stream 2 rows/warp to smem, per-row 1/||x||, colsum partial ===
    // (R10 structure: 32 warps -> 16 smem buffers -> 512 global REDs)
    float rinv0, rinv1;
    {
        const float4* r0 = x4 + (size_t)(blockIdx.x * 64 + lrow0) * ND4;
        const float4* r1 = r0 + ND4;
        float4 v0[4], v1[4];
        #pragma unroll
        for (int k = 0; k < 4; ++k) v0[k] = r0[lane + 32 * k];
        #pragma unroll
        for (int k = 0; k < 4; ++k) v1[k] = r1[lane + 32 * k];
        #pragma unroll
        for (int k = 0; k < 4; ++k) xs[lrow0 * ND4 + lane + 32 * k] = v0[k];
        #pragma unroll
        for (int k = 0; k < 4; ++k) xs[(lrow0 + 1) * ND4 + lane + 32 * k] = v1[k];

        float sq0 = 0.f, sq1 = 0.f;
        #pragma unroll
        for (int k = 0; k < 4; ++k) {
            sq0 += v0[k].x*v0[k].x + v0[k].y*v0[k].y + v0[k].z*v0[k].z + v0[k].w*v0[k].w;
            sq1 += v1[k].x*v1[k].x + v1[k].y*v1[k].y + v1[k].z*v1[k].z + v1[k].w*v1[k].w;
        }
        #pragma unroll
        for (int o = 16; o; o >>= 1) {
            sq0 += __shfl_xor_sync(0xffffffffu, sq0, o);
            sq1 += __shfl_xor_sync(0xffffffffu, sq1, o);
        }
        rinv0 = rsqrtf(sq0); rinv0 = rinv0 * (1.5f - 0.5f * sq0 * rinv0 * rinv0);
        rinv1 = rsqrtf(sq1); rinv1 = rinv1 * (1.5f - 0.5f * sq1 * rinv1 * rinv1);

        float4 acc[4];
        #pragma unroll
        for (int k = 0; k < 4; ++k) {
            acc[k].x = fmaf(v0[k].x, rinv0, v1[k].x * rinv1);
            acc[k].y = fmaf(v0[k].y, rinv0, v1[k].y * rinv1);
            acc[k].z = fmaf(v0[k].z, rinv0, v1[k].z * rinv1);
            acc[k].w = fmaf(v0[k].w, rinv0, v1[k].w * rinv1);
        }
        if (wid >= 16) {
            #pragma unroll
            for (int k = 0; k < 4; ++k) sacc[(wid - 16) * ND4 + lane + 32 * k] = acc[k];
        }
        __syncthreads();
        if (wid < 16) {
            #pragma unroll
            for (int k = 0; k < 4; ++k) {
                float4 o = sacc[wid * ND4 + lane + 32 * k];
                acc[k].x += o.x; acc[k].y += o.y; acc[k].z += o.z; acc[k].w += o.w;
                sacc[wid * ND4 + lane + 32 * k] = acc[k];
            }
        }
        __syncthreads();
        if (t < ND4) {
            float4 s = sacc[t];
            #pragma unroll
            for (int w = 1; w < 16; ++w) {
                float4 u = sacc[w * ND4 + t];
                s.x += u.x; s.y += u.y; s.z += u.z; s.w += u.w;
            }
            sacc[t] = s;
        }
        __syncthreads();
        // 512 REDs per block (one per address) — 128 conflicts/address chip-wide
        if (t < NDIM) atomicAdd((float*)g_s4 + t, saccf[t]);
    }

    // ===== SYNC 1: counter == NBLK  =>  all REDs to g_s complete ==============
    __syncthreads();
    if (t == 0) {
        __threadfence();
        atomicAdd(&g_sync[0], 1u);
        while (vload(&g_sync[0]) < NBLK) __nanosleep(32);
        __threadfence();
    }
    __syncthreads();

    // ===== P3: s direct from L2; dots from smem x; keys + global hist ========
    {
        float4 sv[4];
        #pragma unroll
        for (int k = 0; k < 4; ++k) sv[k] = g_s4[lane + 32 * k];

        float dot0 = 0.f, dot1 = 0.f;
        #pragma unroll
        for (int k = 0; k < 4; ++k) {
            float4 a = xs[lrow0 * ND4 + lane + 32 * k];
            float4 b = xs[(lrow0 + 1) * ND4 + lane + 32 * k];
            dot0 = fmaf(a.x, sv[k].x, dot0); dot0 = fmaf(a.y, sv[k].y, dot0);
            dot0 = fmaf(a.z, sv[k].z, dot0); dot0 = fmaf(a.w, sv[k].w, dot0);
            dot1 = fmaf(b.x, sv[k].x, dot1); dot1 = fmaf(b.y, sv[k].y, dot1);
            dot1 = fmaf(b.z, sv[k].z, dot1); dot1 = fmaf(b.w, sv[k].w, dot1);
        }
        #pragma unroll
        for (int o = 16; o; o >>= 1) {
            dot0 += __shfl_down_sync(0xffffffffu, dot0, o);
            dot1 += __shfl_down_sync(0xffffffffu, dot1, o);
        }
        if (lane == 0) {
            unsigned int u0 = __float_as_uint(dot0 * rinv0);
            unsigned int u1 = __float_as_uint(dot1 * rinv1);
            u0 = (u0 & 0x80000000u) ? ~u0 : (u0 | 0x80000000u);
            u1 = (u1 & 0x80000000u) ? ~u1 : (u1 | 0x80000000u);
            int row = blockIdx.x * 64 + lrow0;
            *(uint2*)&g_key[row] = make_uint2(u0, u1);
            atomicAdd(&g_hist[u0 >> 20], 1);
            atomicAdd(&g_hist[u1 >> 20], 1);
        }
    }

    // ===== SYNC 2: keys + hist visible. Blocks >= NTOP just arrive. ===========
    __syncthreads();
    if (t == 0) { __threadfence(); atomicAdd(&g_sync[1], 1u); }

    if (blockIdx.x < NTOP) {
        if (t == 0) {
            while (vload(&g_sync[1]) < NBLK) __nanosleep(32);
            __threadfence();
        }
        __syncthreads();

        // ===== P4: hist scan -> boundary bin B; collect; exact stable rank ====
        unsigned int* ckey = (unsigned int*)sacc;          // [CAP]
        int*          cidx = (int*)sacc + CAP;             // [CAP]

        uint4 ka = ((const uint4*)g_key)[t];               // keys 4t..4t+3
        uint4 kb = ((const uint4*)g_key)[t + 1024];        // keys 4096+4t..
        uint4 hv = ((const uint4*)g_hist)[t];              // bins 4t..4t+3
        if (t == 0) sh_ncand = 0;

        int lsum = hv.x + hv.y + hv.z + hv.w;
        int v = lsum;
        #pragma unroll
        for (int o = 1; o < 32; o <<= 1) {
            int u = __shfl_up_sync(0xffffffffu, v, o);
            if (lane >= o) v += u;
        }
        if (lane == 31) swarp[wid] = v;
        __syncthreads();
        if (t < 32) {
            int w = swarp[t];
            int vv = w;
            #pragma unroll
            for (int o = 1; o < 32; o <<= 1) {
                int u = __shfl_up_sync(0xffffffffu, vv, o);
                if (lane >= o) vv += u;
            }
            swarp[t] = vv - w;                  // exclusive warp offset
        }
        __syncthreads();
        {
            int c = swarp[wid] + (v - lsum);    // exclusive prefix for bin 4t
            int hh[4] = {(int)hv.x, (int)hv.y, (int)hv.z, (int)hv.w};
            #pragma unroll
            for (int i = 0; i < 4; ++i) {
                int c2 = c + hh[i];
                if (c < NTOP && c2 >= NTOP) sh_B = 4 * t + i;
                c = c2;
            }
        }
        __syncthreads();
        unsigned int B = (unsigned int)sh_B;

        unsigned int keys[8] = {ka.x, ka.y, ka.z, ka.w, kb.x, kb.y, kb.z, kb.w};
        #pragma unroll
        for (int j = 0; j < 8; ++j) {
            if ((keys[j] >> 20) <= B) {
                int p = atomicAdd(&sh_ncand, 1);
                if (p < CAP) {
                    ckey[p] = keys[j];
                    cidx[p] = (j < 4) ? (4 * t + j) : (4096 + 4 * t + (j - 4));
                }
            }
        }
        __syncthreads();
        int nc = sh_ncand < CAP ? sh_ncand : CAP;

        if (t < nc) {
            unsigned int mk = ckey[t];
            int mi = cidx[t];
            int rank = 0;
            for (int j = 0; j < nc; ++j)
                rank += (ckey[j] < mk || (ckey[j] == mk && cidx[j] < mi)) ? 1 : 0;
            if (rank == blockIdx.x) s_row = mi;
        }
        __syncthreads();

        // ===== P5: write this block's row + index ==============================
        int row = s_row;
        if (t < ND4) {
            int e = blockIdx.x * ND4 + t;
            if (4 * e + 4 <= out_size)
                out4[e] = x4[(size_t)row * ND4 + t];
        }
        if (t == 0 && NTOP * NDIM + blockIdx.x < out_size)
            out[NTOP * NDIM + blockIdx.x] = (float)row;
    }

    // ===== epilogue: last finisher resets g_s, g_hist, sync for replay ========
    __shared__ int s_reset;
    if (t == 0) {
        __threadfence();
        s_reset = (atomicAdd(&g_sync[2], 1u) == NBLK - 1) ? 1 : 0;
    }
    __syncthreads();
    if (s_reset) {
        if (t < ND4) g_s4[t] = make_float4(0.f, 0.f, 0.f, 0.f);
        #pragma unroll
        for (int j = 0; j < NBIN / NTHR; ++j) g_hist[t + NTHR * j] = 0;
        __syncthreads();
        if (t == 0) {
            *(volatile unsigned int*)&g_sync[0] = 0;
            *(volatile unsigned int*)&g_sync[1] = 0;
            __threadfence();
            *(volatile unsigned int*)&g_sync[2] = 0;
        }
    }
}

extern "C" void kernel_launch(void* const* d_in, const int* in_sizes, int n_in,
                              void* d_out, int out_size) {
    const float4* x4 = (const float4*)d_in[0];
    cudaFuncSetAttribute(kFused, cudaFuncAttributeMaxDynamicSharedMemorySize,
                         SMEM_TOTAL);
    kFused<<<NBLK, NTHR, SMEM_TOTAL>>>(x4, (float*)d_out, (float4*)d_out, out_size);
}